// round 5
// baseline (speedup 1.0000x reference)
#include <cuda_runtime.h>
#include <math.h>

// ---- problem constants ----
#define HID    2048
#define NH     32
#define KVH    8
#define HD     64
#define BATCH  2
#define SEQ    2048
#define MROWS  (BATCH * SEQ)   // 4096
#define KVDIM  (KVH * HD)      // 512

// ---- scratch (device globals: allocation-free) ----
__device__ float g_q[(size_t)MROWS * HID];
__device__ float g_k[(size_t)MROWS * KVDIM];
__device__ float g_v[(size_t)MROWS * KVDIM];
__device__ float g_att[(size_t)MROWS * HID];

// ============================================================
// SGEMM: C[M,N] = A[M,K] @ B[K,N], all row-major, fp32.
// BM=BN=128, BK=16, 256 threads, 8x8 microtile per thread.
// All dims here are multiples of the tile sizes (asserted by use).
// ============================================================
__global__ void __launch_bounds__(256)
sgemm_kernel(const float* __restrict__ A, const float* __restrict__ Bm,
             float* __restrict__ C, int M, int N, int K)
{
    __shared__ float As[16][128 + 4];   // transposed A tile, padded
    __shared__ float Bs[16][128];

    const int tid = threadIdx.x;
    const int tx = tid & 15;
    const int ty = tid >> 4;
    const int rowBase = blockIdx.y * 128;
    const int colBase = blockIdx.x * 128;

    float acc[8][8];
#pragma unroll
    for (int i = 0; i < 8; ++i)
#pragma unroll
        for (int j = 0; j < 8; ++j) acc[i][j] = 0.0f;

    for (int kt = 0; kt < K; kt += 16) {
        // load A tile (128x16) -> As[k][m]
#pragma unroll
        for (int p = 0; p < 2; ++p) {
            int id = tid + p * 256;
            int arow = id >> 2;       // 0..127
            int ac4 = id & 3;         // 0..3
            float4 v = *(const float4*)&A[(size_t)(rowBase + arow) * K + kt + ac4 * 4];
            As[ac4 * 4 + 0][arow] = v.x;
            As[ac4 * 4 + 1][arow] = v.y;
            As[ac4 * 4 + 2][arow] = v.z;
            As[ac4 * 4 + 3][arow] = v.w;
        }
        // load B tile (16x128) -> Bs[k][n]
#pragma unroll
        for (int p = 0; p < 2; ++p) {
            int id = tid + p * 256;
            int brow = id >> 5;       // 0..15
            int bc4 = id & 31;        // 0..31
            *(float4*)&Bs[brow][bc4 * 4] =
                *(const float4*)&Bm[(size_t)(kt + brow) * N + colBase + bc4 * 4];
        }
        __syncthreads();

#pragma unroll
        for (int k = 0; k < 16; ++k) {
            float a[8], b[8];
            *(float4*)&a[0] = *(const float4*)&As[k][ty * 8];
            *(float4*)&a[4] = *(const float4*)&As[k][ty * 8 + 4];
            *(float4*)&b[0] = *(const float4*)&Bs[k][tx * 8];
            *(float4*)&b[4] = *(const float4*)&Bs[k][tx * 8 + 4];
#pragma unroll
            for (int i = 0; i < 8; ++i)
#pragma unroll
                for (int j = 0; j < 8; ++j)
                    acc[i][j] += a[i] * b[j];
        }
        __syncthreads();
    }

#pragma unroll
    for (int i = 0; i < 8; ++i) {
        size_t r = (size_t)(rowBase + ty * 8 + i);
#pragma unroll
        for (int j = 0; j < 8; j += 4) {
            float4 v = make_float4(acc[i][j], acc[i][j + 1], acc[i][j + 2], acc[i][j + 3]);
            *(float4*)&C[r * N + colBase + tx * 8 + j] = v;
        }
    }
}

// ============================================================
// RoPE applied in place to q [MROWS, NH*HD] and k [MROWS, KVH*HD].
// pair j in [0,32): out[j]    = x[j]*cos - x[j+32]*sin
//                   out[j+32] = x[j+32]*cos + x[j]*sin
// angle = pos * 10000^(-j/32)
// ============================================================
__global__ void rope_kernel(float* __restrict__ q, float* __restrict__ k)
{
    const int QP = MROWS * NH * (HD / 2);
    const int KP = MROWS * KVH * (HD / 2);
    int idx = blockIdx.x * blockDim.x + threadIdx.x;
    if (idx >= QP + KP) return;

    float* buf;
    int row, head, j, rowdim;
    if (idx < QP) {
        int t = idx;
        j = t & 31; t >>= 5;
        head = t & (NH - 1); t >>= 5;   // NH = 32
        row = t;
        buf = q; rowdim = NH * HD;
    } else {
        int t = idx - QP;
        j = t & 31; t >>= 5;
        head = t & (KVH - 1); t >>= 3;  // KVH = 8
        row = t;
        buf = k; rowdim = KVH * HD;
    }
    int pos = row & (SEQ - 1);  // row = b*SEQ + s, SEQ power of 2
    // inv_freq = 10000^(-j/32) = exp2(-j * log2(10000)/32)
    float inv_freq = exp2f(-(float)j * 0.41524101186092029f);
    float ang = (float)pos * inv_freq;
    float c, s;
    __sincosf(ang, &s, &c);
    // NOTE: __sincosf(ang,&s,&c) fast path is too inaccurate for large args; use precise:
    sincosf(ang, &s, &c);

    float* p = buf + (size_t)row * rowdim + head * HD + j;
    float x1 = p[0], x2 = p[32];
    p[0]  = x1 * c - x2 * s;
    p[32] = x2 * c + x1 * s;
}

// ============================================================
// Flash attention, non-causal, GQA (4 q-heads per kv-head).
// Grid: (SEQ/64, NH, BATCH). 256 threads = 16x16, 4x4 microtiles.
// Dynamic smem: Qs[64][64] + Kts[64][64] + Vs[64][64] + Ps[64][64] = 64 KB.
// Kts is d-major with float4-group XOR swizzle for conflict-free reads.
// ============================================================
__global__ void __launch_bounds__(256)
attn_kernel(const float* __restrict__ q, const float* __restrict__ k,
            const float* __restrict__ v, float* __restrict__ o)
{
    extern __shared__ float sm[];
    float* Qs  = sm;                // [64][64] row-major (m, d)
    float* Kts = sm + 64 * 64;      // [64][64] d-major (d, n), swizzled
    float* Vs  = sm + 2 * 64 * 64;  // [64][64] row-major (n, d)
    float* Ps  = sm + 3 * 64 * 64;  // [64][64] row-major (m, n)

    const int tid = threadIdx.x;
    const int tx = tid & 15;
    const int ty = tid >> 4;
    const int qb = blockIdx.x * 64;
    const int h  = blockIdx.y;
    const int b  = blockIdx.z;
    const int kvh = h >> 2;

    const float* qg = q + (size_t)b * SEQ * HID + (size_t)h * HD;
    const float* kg = k + (size_t)b * SEQ * KVDIM + (size_t)kvh * HD;
    const float* vg = v + (size_t)b * SEQ * KVDIM + (size_t)kvh * HD;
    float* og = o + (size_t)b * SEQ * HID + (size_t)h * HD;

    // load Q tile, folding in 1/sqrt(64) = 0.125 scale
#pragma unroll
    for (int p = 0; p < 4; ++p) {
        int id = tid + p * 256;
        int m = id >> 4, d4 = id & 15;
        float4 vq = *(const float4*)&qg[(size_t)(qb + m) * HID + d4 * 4];
        vq.x *= 0.125f; vq.y *= 0.125f; vq.z *= 0.125f; vq.w *= 0.125f;
        *(float4*)&Qs[m * 64 + d4 * 4] = vq;
    }

    float acc[4][4];
    float mi[4], li[4];
#pragma unroll
    for (int r = 0; r < 4; ++r) {
        mi[r] = -3.0e38f;
        li[r] = 0.0f;
#pragma unroll
        for (int c = 0; c < 4; ++c) acc[r][c] = 0.0f;
    }

    for (int kb = 0; kb < SEQ; kb += 64) {
        __syncthreads();  // guards Qs(load) + Kts/Vs/Ps reuse across iterations

        // load K (transposed+swizzled) and V tiles
#pragma unroll
        for (int p = 0; p < 4; ++p) {
            int id = tid + p * 256;
            int n = id >> 4, d4 = id & 15;
            float4 kv = *(const float4*)&kg[(size_t)(kb + n) * KVDIM + d4 * 4];
            float vals[4] = {kv.x, kv.y, kv.z, kv.w};
#pragma unroll
            for (int i = 0; i < 4; ++i) {
                int d = d4 * 4 + i;
                Kts[d * 64 + ((((n >> 2) ^ (d & 15)) << 2) | (n & 3))] = vals[i];
            }
            float4 vv = *(const float4*)&vg[(size_t)(kb + n) * KVDIM + d4 * 4];
            *(float4*)&Vs[n * 64 + d4 * 4] = vv;
        }
        __syncthreads();

        // scores S = Q K^T (already scaled)
        float sc[4][4];
#pragma unroll
        for (int r = 0; r < 4; ++r)
#pragma unroll
            for (int c = 0; c < 4; ++c) sc[r][c] = 0.0f;

#pragma unroll 16
        for (int d = 0; d < 64; ++d) {
            float4 kc = *(const float4*)&Kts[d * 64 + ((tx ^ (d & 15)) << 2)];
            float q0 = Qs[(4 * ty + 0) * 64 + d];
            float q1 = Qs[(4 * ty + 1) * 64 + d];
            float q2 = Qs[(4 * ty + 2) * 64 + d];
            float q3 = Qs[(4 * ty + 3) * 64 + d];
            sc[0][0] += q0 * kc.x; sc[0][1] += q0 * kc.y; sc[0][2] += q0 * kc.z; sc[0][3] += q0 * kc.w;
            sc[1][0] += q1 * kc.x; sc[1][1] += q1 * kc.y; sc[1][2] += q1 * kc.z; sc[1][3] += q1 * kc.w;
            sc[2][0] += q2 * kc.x; sc[2][1] += q2 * kc.y; sc[2][2] += q2 * kc.z; sc[2][3] += q2 * kc.w;
            sc[3][0] += q3 * kc.x; sc[3][1] += q3 * kc.y; sc[3][2] += q3 * kc.z; sc[3][3] += q3 * kc.w;
        }

        // online softmax update (row reduction across the 16 tx lanes)
#pragma unroll
        for (int r = 0; r < 4; ++r) {
            float m = fmaxf(fmaxf(sc[r][0], sc[r][1]), fmaxf(sc[r][2], sc[r][3]));
            m = fmaxf(m, __shfl_xor_sync(0xffffffffu, m, 1));
            m = fmaxf(m, __shfl_xor_sync(0xffffffffu, m, 2));
            m = fmaxf(m, __shfl_xor_sync(0xffffffffu, m, 4));
            m = fmaxf(m, __shfl_xor_sync(0xffffffffu, m, 8));
            float mnew = fmaxf(mi[r], m);
            float alpha = __expf(mi[r] - mnew);
            mi[r] = mnew;
            float rs = 0.0f;
#pragma unroll
            for (int c = 0; c < 4; ++c) {
                sc[r][c] = __expf(sc[r][c] - mnew);
                rs += sc[r][c];
            }
            rs += __shfl_xor_sync(0xffffffffu, rs, 1);
            rs += __shfl_xor_sync(0xffffffffu, rs, 2);
            rs += __shfl_xor_sync(0xffffffffu, rs, 4);
            rs += __shfl_xor_sync(0xffffffffu, rs, 8);
            li[r] = li[r] * alpha + rs;
#pragma unroll
            for (int c = 0; c < 4; ++c) acc[r][c] *= alpha;
            *(float4*)&Ps[(4 * ty + r) * 64 + 4 * tx] =
                make_float4(sc[r][0], sc[r][1], sc[r][2], sc[r][3]);
        }
        __syncthreads();

        // O += P @ V
#pragma unroll 16
        for (int kk = 0; kk < 64; ++kk) {
            float4 vv = *(const float4*)&Vs[kk * 64 + 4 * tx];
            float p0 = Ps[(4 * ty + 0) * 64 + kk];
            float p1 = Ps[(4 * ty + 1) * 64 + kk];
            float p2 = Ps[(4 * ty + 2) * 64 + kk];
            float p3 = Ps[(4 * ty + 3) * 64 + kk];
            acc[0][0] += p0 * vv.x; acc[0][1] += p0 * vv.y; acc[0][2] += p0 * vv.z; acc[0][3] += p0 * vv.w;
            acc[1][0] += p1 * vv.x; acc[1][1] += p1 * vv.y; acc[1][2] += p1 * vv.z; acc[1][3] += p1 * vv.w;
            acc[2][0] += p2 * vv.x; acc[2][1] += p2 * vv.y; acc[2][2] += p2 * vv.z; acc[2][3] += p2 * vv.w;
            acc[3][0] += p3 * vv.x; acc[3][1] += p3 * vv.y; acc[3][2] += p3 * vv.z; acc[3][3] += p3 * vv.w;
        }
    }

    // epilogue: normalize and store [b, s, h, d]
#pragma unroll
    for (int r = 0; r < 4; ++r) {
        float inv = 1.0f / li[r];
        float4 ov = make_float4(acc[r][0] * inv, acc[r][1] * inv,
                                acc[r][2] * inv, acc[r][3] * inv);
        *(float4*)&og[(size_t)(qb + 4 * ty + r) * HID + 4 * tx] = ov;
    }
}

// ============================================================
// launch
// ============================================================
extern "C" void kernel_launch(void* const* d_in, const int* in_sizes, int n_in,
                              void* d_out, int out_size)
{
    const float* x  = (const float*)d_in[0];
    const float* wq = (const float*)d_in[1];
    const float* wk = (const float*)d_in[2];
    const float* wv = (const float*)d_in[3];
    const float* wo = (const float*)d_in[4];
    float* out = (float*)d_out;

    float *qp, *kp, *vp, *ap;
    cudaGetSymbolAddress((void**)&qp, g_q);
    cudaGetSymbolAddress((void**)&kp, g_k);
    cudaGetSymbolAddress((void**)&vp, g_v);
    cudaGetSymbolAddress((void**)&ap, g_att);

    dim3 blk(256);

    // QKV projections
    sgemm_kernel<<<dim3(HID / 128, MROWS / 128), blk>>>(x, wq, qp, MROWS, HID, HID);
    sgemm_kernel<<<dim3(KVDIM / 128, MROWS / 128), blk>>>(x, wk, kp, MROWS, KVDIM, HID);
    sgemm_kernel<<<dim3(KVDIM / 128, MROWS / 128), blk>>>(x, wv, vp, MROWS, KVDIM, HID);

    // RoPE (q and k in place)
    int total = MROWS * NH * (HD / 2) + MROWS * KVH * (HD / 2);
    rope_kernel<<<(total + 255) / 256, 256>>>(qp, kp);

    // attention
    cudaFuncSetAttribute(attn_kernel, cudaFuncAttributeMaxDynamicSharedMemorySize, 65536);
    attn_kernel<<<dim3(SEQ / 64, NH, BATCH), blk, 65536>>>(qp, kp, vp, ap);

    // output projection -> d_out
    sgemm_kernel<<<dim3(HID / 128, MROWS / 128), blk>>>(ap, wo, out, MROWS, HID, HID);
}

// round 6
// speedup vs baseline: 1.0088x; 1.0088x over previous
#include <cuda_runtime.h>
#include <math.h>

// ---- problem constants ----
#define HID    2048
#define NH     32
#define KVH    8
#define HD     64
#define BATCH  2
#define SEQ    2048
#define MROWS  (BATCH * SEQ)   // 4096
#define KVDIM  (KVH * HD)      // 512

typedef unsigned long long u64;

// ---- packed f32x2 helpers (Blackwell-only PTX; 2 FMAs per issue) ----
__device__ __forceinline__ u64 dup2(float x) {
    u64 r;
    unsigned xi = __float_as_uint(x);
    asm("mov.b64 %0, {%1, %1};" : "=l"(r) : "r"(xi));
    return r;
}
__device__ __forceinline__ void fma2(u64& d, u64 a, u64 b) {
    asm("fma.rn.f32x2 %0, %1, %2, %0;" : "+l"(d) : "l"(a), "l"(b));
}
__device__ __forceinline__ void mul2(u64& d, u64 a) {
    asm("mul.rn.f32x2 %0, %0, %1;" : "+l"(d) : "l"(a));
}
__device__ __forceinline__ float2 unpack2(u64 v) {
    unsigned lo, hi;
    asm("mov.b64 {%0, %1}, %2;" : "=r"(lo), "=r"(hi) : "l"(v));
    return make_float2(__uint_as_float(lo), __uint_as_float(hi));
}

// ---- scratch (device globals: allocation-free) ----
__device__ float g_q[(size_t)MROWS * HID];
__device__ float g_k[(size_t)MROWS * KVDIM];
__device__ float g_v[(size_t)MROWS * KVDIM];
__device__ float g_att[(size_t)MROWS * HID];

// ============================================================
// SGEMM: C[M,N] = A[M,K] @ B[K,N], row-major fp32.
// BM=BN=128, BK=16, 256 threads, 8x8 microtile, f32x2 packed FMA.
// ============================================================
__global__ void __launch_bounds__(256)
sgemm_kernel(const float* __restrict__ A, const float* __restrict__ Bm,
             float* __restrict__ C, int M, int N, int K)
{
    __shared__ float As[16][128 + 4];   // transposed A tile, padded
    __shared__ float Bs[16][128];

    const int tid = threadIdx.x;
    const int tx = tid & 15;
    const int ty = tid >> 4;
    const int rowBase = blockIdx.y * 128;
    const int colBase = blockIdx.x * 128;

    // packed accumulators: acc[i][jp] holds columns (2*jp, 2*jp+1)
    u64 acc[8][4];
#pragma unroll
    for (int i = 0; i < 8; ++i)
#pragma unroll
        for (int j = 0; j < 4; ++j) acc[i][j] = 0ULL;  // bits of (0.f, 0.f)

    for (int kt = 0; kt < K; kt += 16) {
        // load A tile (128x16) -> As[k][m]
#pragma unroll
        for (int p = 0; p < 2; ++p) {
            int id = tid + p * 256;
            int arow = id >> 2;       // 0..127
            int ac4 = id & 3;         // 0..3
            float4 v = *(const float4*)&A[(size_t)(rowBase + arow) * K + kt + ac4 * 4];
            As[ac4 * 4 + 0][arow] = v.x;
            As[ac4 * 4 + 1][arow] = v.y;
            As[ac4 * 4 + 2][arow] = v.z;
            As[ac4 * 4 + 3][arow] = v.w;
        }
        // load B tile (16x128) -> Bs[k][n]
#pragma unroll
        for (int p = 0; p < 2; ++p) {
            int id = tid + p * 256;
            int brow = id >> 5;       // 0..15
            int bc4 = id & 31;        // 0..31
            *(float4*)&Bs[brow][bc4 * 4] =
                *(const float4*)&Bm[(size_t)(kt + brow) * N + colBase + bc4 * 4];
        }
        __syncthreads();

#pragma unroll
        for (int k = 0; k < 16; ++k) {
            float a[8];
            *(float4*)&a[0] = *(const float4*)&As[k][ty * 8];
            *(float4*)&a[4] = *(const float4*)&As[k][ty * 8 + 4];
            u64 ap[8];
#pragma unroll
            for (int i = 0; i < 8; ++i) ap[i] = dup2(a[i]);

            const u64* bpr = (const u64*)&Bs[k][tx * 8];   // 4x LDS.64, pairs
            u64 bp0 = bpr[0], bp1 = bpr[1], bp2 = bpr[2], bp3 = bpr[3];
#pragma unroll
            for (int i = 0; i < 8; ++i) {
                fma2(acc[i][0], ap[i], bp0);
                fma2(acc[i][1], ap[i], bp1);
                fma2(acc[i][2], ap[i], bp2);
                fma2(acc[i][3], ap[i], bp3);
            }
        }
        __syncthreads();
    }

#pragma unroll
    for (int i = 0; i < 8; ++i) {
        size_t r = (size_t)(rowBase + ty * 8 + i);
        float2 c0 = unpack2(acc[i][0]);
        float2 c1 = unpack2(acc[i][1]);
        float2 c2 = unpack2(acc[i][2]);
        float2 c3 = unpack2(acc[i][3]);
        *(float4*)&C[r * N + colBase + tx * 8]     = make_float4(c0.x, c0.y, c1.x, c1.y);
        *(float4*)&C[r * N + colBase + tx * 8 + 4] = make_float4(c2.x, c2.y, c3.x, c3.y);
    }
}

// ============================================================
// RoPE applied in place to q [MROWS, NH*HD] and k [MROWS, KVH*HD].
// ============================================================
__global__ void rope_kernel(float* __restrict__ q, float* __restrict__ k)
{
    const int QP = MROWS * NH * (HD / 2);
    const int KP = MROWS * KVH * (HD / 2);
    int idx = blockIdx.x * blockDim.x + threadIdx.x;
    if (idx >= QP + KP) return;

    float* buf;
    int row, head, j, rowdim;
    if (idx < QP) {
        int t = idx;
        j = t & 31; t >>= 5;
        head = t & (NH - 1); t >>= 5;   // NH = 32
        row = t;
        buf = q; rowdim = NH * HD;
    } else {
        int t = idx - QP;
        j = t & 31; t >>= 5;
        head = t & (KVH - 1); t >>= 3;  // KVH = 8
        row = t;
        buf = k; rowdim = KVH * HD;
    }
    int pos = row & (SEQ - 1);
    float inv_freq = exp2f(-(float)j * 0.41524101186092029f);
    float ang = (float)pos * inv_freq;
    float c, s;
    sincosf(ang, &s, &c);

    float* p = buf + (size_t)row * rowdim + head * HD + j;
    float x1 = p[0], x2 = p[32];
    p[0]  = x1 * c - x2 * s;
    p[32] = x2 * c + x1 * s;
}

// ============================================================
// Flash attention, non-causal, GQA. f32x2 packed FMA mainloops.
// Grid: (SEQ/64, NH, BATCH). 256 threads = 16x16, 4x4 microtiles.
// ============================================================
__global__ void __launch_bounds__(256)
attn_kernel(const float* __restrict__ q, const float* __restrict__ k,
            const float* __restrict__ v, float* __restrict__ o)
{
    extern __shared__ float sm[];
    float* Qs  = sm;                // [64][64] row-major (m, d)
    float* Kts = sm + 64 * 64;      // [64][64] d-major (d, n), swizzled
    float* Vs  = sm + 2 * 64 * 64;  // [64][64] row-major (n, d)
    float* Ps  = sm + 3 * 64 * 64;  // [64][64] row-major (m, n)

    const int tid = threadIdx.x;
    const int tx = tid & 15;
    const int ty = tid >> 4;
    const int qb = blockIdx.x * 64;
    const int h  = blockIdx.y;
    const int b  = blockIdx.z;
    const int kvh = h >> 2;

    const float* qg = q + (size_t)b * SEQ * HID + (size_t)h * HD;
    const float* kg = k + (size_t)b * SEQ * KVDIM + (size_t)kvh * HD;
    const float* vg = v + (size_t)b * SEQ * KVDIM + (size_t)kvh * HD;
    float* og = o + (size_t)b * SEQ * HID + (size_t)h * HD;

    // load Q tile, folding in 1/sqrt(64) = 0.125 scale
#pragma unroll
    for (int p = 0; p < 4; ++p) {
        int id = tid + p * 256;
        int m = id >> 4, d4 = id & 15;
        float4 vq = *(const float4*)&qg[(size_t)(qb + m) * HID + d4 * 4];
        vq.x *= 0.125f; vq.y *= 0.125f; vq.z *= 0.125f; vq.w *= 0.125f;
        *(float4*)&Qs[m * 64 + d4 * 4] = vq;
    }

    u64 accp[4][2];           // packed O accumulators: [row][pair of d-cols]
    float mi[4], li[4];
#pragma unroll
    for (int r = 0; r < 4; ++r) {
        mi[r] = -3.0e38f;
        li[r] = 0.0f;
        accp[r][0] = 0ULL;
        accp[r][1] = 0ULL;
    }

    for (int kb = 0; kb < SEQ; kb += 64) {
        __syncthreads();  // guards Qs(load) + Kts/Vs/Ps reuse across iterations

        // load K (transposed+swizzled) and V tiles
#pragma unroll
        for (int p = 0; p < 4; ++p) {
            int id = tid + p * 256;
            int n = id >> 4, d4 = id & 15;
            float4 kv = *(const float4*)&kg[(size_t)(kb + n) * KVDIM + d4 * 4];
            float vals[4] = {kv.x, kv.y, kv.z, kv.w};
#pragma unroll
            for (int i = 0; i < 4; ++i) {
                int d = d4 * 4 + i;
                Kts[d * 64 + ((((n >> 2) ^ (d & 15)) << 2) | (n & 3))] = vals[i];
            }
            float4 vv = *(const float4*)&vg[(size_t)(kb + n) * KVDIM + d4 * 4];
            *(float4*)&Vs[n * 64 + d4 * 4] = vv;
        }
        __syncthreads();

        // scores S = Q K^T (already scaled), packed pairs along n
        u64 scp[4][2];
#pragma unroll
        for (int r = 0; r < 4; ++r) { scp[r][0] = 0ULL; scp[r][1] = 0ULL; }

#pragma unroll 16
        for (int d = 0; d < 64; ++d) {
            const u64* kp = (const u64*)&Kts[d * 64 + ((tx ^ (d & 15)) << 2)];
            u64 k0 = kp[0], k1 = kp[1];
            u64 q0 = dup2(Qs[(4 * ty + 0) * 64 + d]);
            u64 q1 = dup2(Qs[(4 * ty + 1) * 64 + d]);
            u64 q2 = dup2(Qs[(4 * ty + 2) * 64 + d]);
            u64 q3 = dup2(Qs[(4 * ty + 3) * 64 + d]);
            fma2(scp[0][0], q0, k0); fma2(scp[0][1], q0, k1);
            fma2(scp[1][0], q1, k0); fma2(scp[1][1], q1, k1);
            fma2(scp[2][0], q2, k0); fma2(scp[2][1], q2, k1);
            fma2(scp[3][0], q3, k0); fma2(scp[3][1], q3, k1);
        }

        // online softmax update (row reduction across the 16 tx lanes)
#pragma unroll
        for (int r = 0; r < 4; ++r) {
            float2 s01 = unpack2(scp[r][0]);
            float2 s23 = unpack2(scp[r][1]);
            float sc0 = s01.x, sc1 = s01.y, sc2 = s23.x, sc3 = s23.y;

            float m = fmaxf(fmaxf(sc0, sc1), fmaxf(sc2, sc3));
            m = fmaxf(m, __shfl_xor_sync(0xffffffffu, m, 1));
            m = fmaxf(m, __shfl_xor_sync(0xffffffffu, m, 2));
            m = fmaxf(m, __shfl_xor_sync(0xffffffffu, m, 4));
            m = fmaxf(m, __shfl_xor_sync(0xffffffffu, m, 8));
            float mnew = fmaxf(mi[r], m);
            float alpha = __expf(mi[r] - mnew);
            mi[r] = mnew;

            sc0 = __expf(sc0 - mnew);
            sc1 = __expf(sc1 - mnew);
            sc2 = __expf(sc2 - mnew);
            sc3 = __expf(sc3 - mnew);
            float rs = sc0 + sc1 + sc2 + sc3;
            rs += __shfl_xor_sync(0xffffffffu, rs, 1);
            rs += __shfl_xor_sync(0xffffffffu, rs, 2);
            rs += __shfl_xor_sync(0xffffffffu, rs, 4);
            rs += __shfl_xor_sync(0xffffffffu, rs, 8);
            li[r] = li[r] * alpha + rs;

            u64 ad = dup2(alpha);
            mul2(accp[r][0], ad);
            mul2(accp[r][1], ad);

            *(float4*)&Ps[(4 * ty + r) * 64 + 4 * tx] = make_float4(sc0, sc1, sc2, sc3);
        }
        __syncthreads();

        // O += P @ V, packed pairs along d
#pragma unroll 16
        for (int kk = 0; kk < 64; ++kk) {
            const u64* vp = (const u64*)&Vs[kk * 64 + 4 * tx];
            u64 v0 = vp[0], v1 = vp[1];
            u64 p0 = dup2(Ps[(4 * ty + 0) * 64 + kk]);
            u64 p1 = dup2(Ps[(4 * ty + 1) * 64 + kk]);
            u64 p2 = dup2(Ps[(4 * ty + 2) * 64 + kk]);
            u64 p3 = dup2(Ps[(4 * ty + 3) * 64 + kk]);
            fma2(accp[0][0], p0, v0); fma2(accp[0][1], p0, v1);
            fma2(accp[1][0], p1, v0); fma2(accp[1][1], p1, v1);
            fma2(accp[2][0], p2, v0); fma2(accp[2][1], p2, v1);
            fma2(accp[3][0], p3, v0); fma2(accp[3][1], p3, v1);
        }
    }

    // epilogue: normalize and store [b, s, h, d]
#pragma unroll
    for (int r = 0; r < 4; ++r) {
        float inv = 1.0f / li[r];
        float2 a01 = unpack2(accp[r][0]);
        float2 a23 = unpack2(accp[r][1]);
        float4 ov = make_float4(a01.x * inv, a01.y * inv, a23.x * inv, a23.y * inv);
        *(float4*)&og[(size_t)(qb + 4 * ty + r) * HID + 4 * tx] = ov;
    }
}

// ============================================================
// launch
// ============================================================
extern "C" void kernel_launch(void* const* d_in, const int* in_sizes, int n_in,
                              void* d_out, int out_size)
{
    const float* x  = (const float*)d_in[0];
    const float* wq = (const float*)d_in[1];
    const float* wk = (const float*)d_in[2];
    const float* wv = (const float*)d_in[3];
    const float* wo = (const float*)d_in[4];
    float* out = (float*)d_out;

    float *qp, *kp, *vp, *ap;
    cudaGetSymbolAddress((void**)&qp, g_q);
    cudaGetSymbolAddress((void**)&kp, g_k);
    cudaGetSymbolAddress((void**)&vp, g_v);
    cudaGetSymbolAddress((void**)&ap, g_att);

    dim3 blk(256);

    // QKV projections
    sgemm_kernel<<<dim3(HID / 128, MROWS / 128), blk>>>(x, wq, qp, MROWS, HID, HID);
    sgemm_kernel<<<dim3(KVDIM / 128, MROWS / 128), blk>>>(x, wk, kp, MROWS, KVDIM, HID);
    sgemm_kernel<<<dim3(KVDIM / 128, MROWS / 128), blk>>>(x, wv, vp, MROWS, KVDIM, HID);

    // RoPE (q and k in place)
    int total = MROWS * NH * (HD / 2) + MROWS * KVH * (HD / 2);
    rope_kernel<<<(total + 255) / 256, 256>>>(qp, kp);

    // attention
    cudaFuncSetAttribute(attn_kernel, cudaFuncAttributeMaxDynamicSharedMemorySize, 65536);
    attn_kernel<<<dim3(SEQ / 64, NH, BATCH), blk, 65536>>>(qp, kp, vp, ap);

    // output projection -> d_out
    sgemm_kernel<<<dim3(HID / 128, MROWS / 128), blk>>>(ap, wo, out, MROWS, HID, HID);
}